// round 2
// baseline (speedup 1.0000x reference)
#include <cuda_runtime.h>
#include <math.h>

#define NB 4096
#define NC 512
#define NHW 196
#define NE 64
#define TOPK 8
#define ROWS 16

// ---------------------------------------------------------------------------
// Fused kernel: pool (16 batch rows -> smem) + routing GEMM + softmax/top-8.
// One block = 16 batch rows, 256 threads. 256 blocks, all co-resident:
// each block's GEMM/top-k hides under other blocks' HBM streaming.
// ---------------------------------------------------------------------------
__global__ __launch_bounds__(256) void fused_router_kernel(
    const float* __restrict__ x,       // [B, C, H, W]
    const float* __restrict__ noise,   // [B, E]
    const float* __restrict__ Wr, const float* __restrict__ br,
    const float* __restrict__ Wn, const float* __restrict__ bn,
    float* __restrict__ out)
{
    __shared__ float sp[ROWS * NC];     // 32 KB pooled tile
    __shared__ float sLog[ROWS][NE];    // 4 KB route logits
    __shared__ float sNse[ROWS][NE];    // 4 KB noise logits

    const int tid  = threadIdx.x;
    const int wid  = tid >> 5;
    const int lane = tid & 31;
    const int b0   = blockIdx.x * ROWS;

    // ---------------- Phase A: pool 16x512 rows of 196 floats ----------------
    // warp-per-row, 2 rows per iteration for ILP on the shuffle-reduce chain.
    const float* base = x + (size_t)b0 * NC * NHW;
    for (int row = wid; row < ROWS * NC; row += 16) {
        const float4* r4a = reinterpret_cast<const float4*>(base + (size_t)row * NHW);
        const float4* r4b = reinterpret_cast<const float4*>(base + (size_t)(row + 8) * NHW);
        float4 a0 = r4a[lane];
        float4 b0v = r4b[lane];
        float s0 = (a0.x + a0.y) + (a0.z + a0.w);
        float s1 = (b0v.x + b0v.y) + (b0v.z + b0v.w);
        if (lane < 17) {
            float4 a1 = r4a[32 + lane];
            float4 b1 = r4b[32 + lane];
            s0 += (a1.x + a1.y) + (a1.z + a1.w);
            s1 += (b1.x + b1.y) + (b1.z + b1.w);
        }
#pragma unroll
        for (int o = 16; o; o >>= 1) {
            s0 += __shfl_xor_sync(0xffffffffu, s0, o);
            s1 += __shfl_xor_sync(0xffffffffu, s1, o);
        }
        if (lane == 0) {
            sp[row]     = s0 * (1.0f / 196.0f);
            sp[row + 8] = s1 * (1.0f / 196.0f);
        }
    }
    __syncthreads();

    // ---------------- Phase B: [16,512] @ [512,64]^T x2 ----------------
    // thread = (expert e, quad q). float4 index j*4+q: conflict-free LDS.128,
    // 8 same-q lanes broadcast. 8 FMAs per LDS.128.
    const int e = tid >> 2;
    const int q = tid & 3;
    float accR[ROWS], accN[ROWS];
#pragma unroll
    for (int r = 0; r < ROWS; r++) { accR[r] = 0.0f; accN[r] = 0.0f; }

    const float4* Wr4 = reinterpret_cast<const float4*>(Wr) + e * (NC / 4);
    const float4* Wn4 = reinterpret_cast<const float4*>(Wn) + e * (NC / 4);
    const float4* sp4 = reinterpret_cast<const float4*>(sp);

#pragma unroll 4
    for (int j = 0; j < NC / 16; j++) {
        const int idx = j * 4 + q;
        float4 wr4 = __ldg(&Wr4[idx]);
        float4 wn4 = __ldg(&Wn4[idx]);
#pragma unroll
        for (int r = 0; r < ROWS; r++) {
            float4 p = sp4[r * (NC / 4) + idx];
            accR[r] = fmaf(p.x, wr4.x, accR[r]);
            accR[r] = fmaf(p.y, wr4.y, accR[r]);
            accR[r] = fmaf(p.z, wr4.z, accR[r]);
            accR[r] = fmaf(p.w, wr4.w, accR[r]);
            accN[r] = fmaf(p.x, wn4.x, accN[r]);
            accN[r] = fmaf(p.y, wn4.y, accN[r]);
            accN[r] = fmaf(p.z, wn4.z, accN[r]);
            accN[r] = fmaf(p.w, wn4.w, accN[r]);
        }
    }
    // reduce across the quad (lanes q=0..3 share expert e)
#pragma unroll
    for (int r = 0; r < ROWS; r++) {
        accR[r] += __shfl_xor_sync(0xffffffffu, accR[r], 1);
        accR[r] += __shfl_xor_sync(0xffffffffu, accR[r], 2);
        accN[r] += __shfl_xor_sync(0xffffffffu, accN[r], 1);
        accN[r] += __shfl_xor_sync(0xffffffffu, accN[r], 2);
    }
    if (q == 0) {
        float brv = br[e], bnv = bn[e];
#pragma unroll
        for (int r = 0; r < ROWS; r++) {
            sLog[r][e] = accR[r] + brv;
            sNse[r][e] = accN[r] + bnv;
        }
    }
    __syncthreads();

    // ---------------- Phase C: softmax + noise + top-8 + renorm ----------------
    float* out_rtr = out;                          // [B,8] router_output
    float* out_idx = out + (size_t)NB * TOPK;      // [B,8] indices (as float)
    float* out_nzy = out + (size_t)2 * NB * TOPK;  // [B,64] noisy_logits

#pragma unroll
    for (int rr = 0; rr < 2; rr++) {
        const int r = wid * 2 + rr;
        const int b = b0 + r;

        float lg0 = sLog[r][lane], lg1 = sLog[r][lane + 32];
        float nl0 = sNse[r][lane], nl1 = sNse[r][lane + 32];

        // softmax(route logits) over 64
        float m = fmaxf(lg0, lg1);
#pragma unroll
        for (int o = 16; o; o >>= 1) m = fmaxf(m, __shfl_xor_sync(0xffffffffu, m, o));
        float e0 = __expf(lg0 - m), e1 = __expf(lg1 - m);
        float s = e0 + e1;
#pragma unroll
        for (int o = 16; o; o >>= 1) s += __shfl_xor_sync(0xffffffffu, s, o);
        float inv = __frcp_rn(s);
        float smL0 = e0 * inv, smL1 = e1 * inv;

        // noise branch: z = noise * softplus(noise_logits); softmax(z)
        float sp0 = fmaxf(nl0, 0.0f) + log1pf(__expf(-fabsf(nl0)));
        float sp1 = fmaxf(nl1, 0.0f) + log1pf(__expf(-fabsf(nl1)));
        float z0 = noise[(size_t)b * NE + lane]      * sp0;
        float z1 = noise[(size_t)b * NE + lane + 32] * sp1;
        float mn = fmaxf(z0, z1);
#pragma unroll
        for (int o = 16; o; o >>= 1) mn = fmaxf(mn, __shfl_xor_sync(0xffffffffu, mn, o));
        float f0 = __expf(z0 - mn), f1 = __expf(z1 - mn);
        float sn = f0 + f1;
#pragma unroll
        for (int o = 16; o; o >>= 1) sn += __shfl_xor_sync(0xffffffffu, sn, o);
        float invn = __frcp_rn(sn);

        float noisy0 = smL0 + f0 * invn;
        float noisy1 = smL1 + f1 * invn;

        out_nzy[(size_t)b * NE + lane]      = noisy0;
        out_nzy[(size_t)b * NE + lane + 32] = noisy1;

        // top-8: iterative warp argmax; tie-break = lowest index (lax.top_k)
        float v0 = noisy0, v1 = noisy1;
        float topv[TOPK];
        int   topi[TOPK];
#pragma unroll
        for (int k = 0; k < TOPK; k++) {
            float bv; int bi;
            if (v0 >= v1) { bv = v0; bi = lane; }
            else          { bv = v1; bi = lane + 32; }
#pragma unroll
            for (int o = 16; o; o >>= 1) {
                float ov = __shfl_xor_sync(0xffffffffu, bv, o);
                int   oi = __shfl_xor_sync(0xffffffffu, bi, o);
                if (ov > bv || (ov == bv && oi < bi)) { bv = ov; bi = oi; }
            }
            topv[k] = bv; topi[k] = bi;
            if      (bi == lane)      v0 = -INFINITY;
            else if (bi == lane + 32) v1 = -INFINITY;
        }

        float ssum = 0.0f, ev[TOPK];
#pragma unroll
        for (int k = 0; k < TOPK; k++) { ev[k] = __expf(topv[k] - topv[0]); ssum += ev[k]; }
        float invt = __frcp_rn(ssum);

#pragma unroll
        for (int k = 0; k < TOPK; k++) {
            if (lane == k) {
                out_rtr[(size_t)b * TOPK + k] = ev[k] * invt;
                out_idx[(size_t)b * TOPK + k] = (float)topi[k];
            }
        }
    }
}

// ---------------------------------------------------------------------------
extern "C" void kernel_launch(void* const* d_in, const int* in_sizes, int n_in,
                              void* d_out, int out_size) {
    const float* mh      = (const float*)d_in[0];
    const float* noise   = (const float*)d_in[1];
    const float* W_route = (const float*)d_in[2];
    const float* b_route = (const float*)d_in[3];
    const float* W_noise = (const float*)d_in[4];
    const float* b_noise = (const float*)d_in[5];
    float* out = (float*)d_out;

    fused_router_kernel<<<NB / ROWS, 256>>>(mh, noise, W_route, b_route,
                                            W_noise, b_noise, out);
}

// round 3
// speedup vs baseline: 1.3560x; 1.3560x over previous
#include <cuda_runtime.h>
#include <math.h>

#define NB 4096
#define NC 512
#define NHW 196
#define NE 64
#define TOPK 8
#define ROWS 8

// scratch: pooled [B, C]  (8 MB) — __device__ global, no allocation
__device__ float g_pooled[NB * NC];

// ---------------------------------------------------------------------------
// Kernel 1: global average pool  [B, C, H, W] -> [B, C]   (round-1 version,
// measured ~6.8 TB/s). One warp per (b,c) row: 196 floats = 49 float4.
// ---------------------------------------------------------------------------
__global__ __launch_bounds__(256) void pool_kernel(const float* __restrict__ x) {
    int warp = (blockIdx.x * 256 + threadIdx.x) >> 5;
    int lane = threadIdx.x & 31;
    if (warp >= NB * NC) return;

    const float4* row4 = reinterpret_cast<const float4*>(x + (size_t)warp * NHW);
    float4 a = row4[lane];
    float s = (a.x + a.y) + (a.z + a.w);
    if (lane < 17) {
        float4 b4 = row4[32 + lane];
        s += (b4.x + b4.y) + (b4.z + b4.w);
    }
#pragma unroll
    for (int o = 16; o; o >>= 1) s += __shfl_xor_sync(0xffffffffu, s, o);
    if (lane == 0) g_pooled[warp] = s * (1.0f / 196.0f);
}

// ---------------------------------------------------------------------------
// Kernel 2: routing. One block = 8 batch rows, 256 threads, grid 512.
// GEMM: thread = (expert e, quad q); conflict-free LDS.128, 8 FMA per LDS.
// Postprocess: one warp per row.
// ---------------------------------------------------------------------------
__global__ __launch_bounds__(256) void router_kernel(
    const float* __restrict__ noise,
    const float* __restrict__ Wr, const float* __restrict__ br,
    const float* __restrict__ Wn, const float* __restrict__ bn,
    float* __restrict__ out)
{
    __shared__ float sp[ROWS * NC];     // 16 KB pooled tile
    __shared__ float sLog[ROWS][NE];    // 2 KB
    __shared__ float sNse[ROWS][NE];    // 2 KB

    const int tid  = threadIdx.x;
    const int wid  = tid >> 5;
    const int lane = tid & 31;
    const int b0   = blockIdx.x * ROWS;

    // load pooled tile with float4 (coalesced, 4 per thread)
    {
        const float4* g4 = reinterpret_cast<const float4*>(g_pooled + (size_t)b0 * NC);
        float4* s4 = reinterpret_cast<float4*>(sp);
#pragma unroll
        for (int i = 0; i < ROWS * NC / 4 / 256; i++)
            s4[tid + i * 256] = g4[tid + i * 256];
    }
    __syncthreads();

    // GEMM: [8,512] @ [512,64]^T x2
    const int e = tid >> 2;
    const int q = tid & 3;
    float accR[ROWS], accN[ROWS];
#pragma unroll
    for (int r = 0; r < ROWS; r++) { accR[r] = 0.0f; accN[r] = 0.0f; }

    const float4* Wr4 = reinterpret_cast<const float4*>(Wr) + e * (NC / 4);
    const float4* Wn4 = reinterpret_cast<const float4*>(Wn) + e * (NC / 4);
    const float4* sp4 = reinterpret_cast<const float4*>(sp);

#pragma unroll 4
    for (int j = 0; j < NC / 16; j++) {
        const int idx = j * 4 + q;                 // quad-interleaved: no bank conflicts
        float4 wr4 = __ldg(&Wr4[idx]);
        float4 wn4 = __ldg(&Wn4[idx]);
#pragma unroll
        for (int r = 0; r < ROWS; r++) {
            float4 p = sp4[r * (NC / 4) + idx];
            accR[r] = fmaf(p.x, wr4.x, accR[r]);
            accR[r] = fmaf(p.y, wr4.y, accR[r]);
            accR[r] = fmaf(p.z, wr4.z, accR[r]);
            accR[r] = fmaf(p.w, wr4.w, accR[r]);
            accN[r] = fmaf(p.x, wn4.x, accN[r]);
            accN[r] = fmaf(p.y, wn4.y, accN[r]);
            accN[r] = fmaf(p.z, wn4.z, accN[r]);
            accN[r] = fmaf(p.w, wn4.w, accN[r]);
        }
    }
    // reduce across the quad (lanes q=0..3 share expert e)
#pragma unroll
    for (int r = 0; r < ROWS; r++) {
        accR[r] += __shfl_xor_sync(0xffffffffu, accR[r], 1);
        accR[r] += __shfl_xor_sync(0xffffffffu, accR[r], 2);
        accN[r] += __shfl_xor_sync(0xffffffffu, accN[r], 1);
        accN[r] += __shfl_xor_sync(0xffffffffu, accN[r], 2);
    }
    if (q == 0) {
        float brv = br[e], bnv = bn[e];
#pragma unroll
        for (int r = 0; r < ROWS; r++) {
            sLog[r][e] = accR[r] + brv;
            sNse[r][e] = accN[r] + bnv;
        }
    }
    __syncthreads();

    // Postprocess: one warp per row; lane owns experts lane, lane+32.
    float* out_rtr = out;                          // [B,8]
    float* out_idx = out + (size_t)NB * TOPK;      // [B,8] as float
    float* out_nzy = out + (size_t)2 * NB * TOPK;  // [B,64]

    const int r = wid;
    const int b = b0 + r;

    float lg0 = sLog[r][lane], lg1 = sLog[r][lane + 32];
    float nl0 = sNse[r][lane], nl1 = sNse[r][lane + 32];

    // softmax(route logits) over 64
    float m = fmaxf(lg0, lg1);
#pragma unroll
    for (int o = 16; o; o >>= 1) m = fmaxf(m, __shfl_xor_sync(0xffffffffu, m, o));
    float e0 = __expf(lg0 - m), e1 = __expf(lg1 - m);
    float s = e0 + e1;
#pragma unroll
    for (int o = 16; o; o >>= 1) s += __shfl_xor_sync(0xffffffffu, s, o);
    float inv = __frcp_rn(s);
    float smL0 = e0 * inv, smL1 = e1 * inv;

    // noise branch
    float sp0 = fmaxf(nl0, 0.0f) + log1pf(__expf(-fabsf(nl0)));
    float sp1 = fmaxf(nl1, 0.0f) + log1pf(__expf(-fabsf(nl1)));
    float z0 = noise[(size_t)b * NE + lane]      * sp0;
    float z1 = noise[(size_t)b * NE + lane + 32] * sp1;
    float mn = fmaxf(z0, z1);
#pragma unroll
    for (int o = 16; o; o >>= 1) mn = fmaxf(mn, __shfl_xor_sync(0xffffffffu, mn, o));
    float f0 = __expf(z0 - mn), f1 = __expf(z1 - mn);
    float sn = f0 + f1;
#pragma unroll
    for (int o = 16; o; o >>= 1) sn += __shfl_xor_sync(0xffffffffu, sn, o);
    float invn = __frcp_rn(sn);

    float noisy0 = smL0 + f0 * invn;
    float noisy1 = smL1 + f1 * invn;

    out_nzy[(size_t)b * NE + lane]      = noisy0;
    out_nzy[(size_t)b * NE + lane + 32] = noisy1;

    // top-8: iterative warp argmax; tie-break = lowest index (lax.top_k)
    float v0 = noisy0, v1 = noisy1;
    float topv[TOPK];
    int   topi[TOPK];
#pragma unroll
    for (int k = 0; k < TOPK; k++) {
        float bv; int bi;
        if (v0 >= v1) { bv = v0; bi = lane; }
        else          { bv = v1; bi = lane + 32; }
#pragma unroll
        for (int o = 16; o; o >>= 1) {
            float ov = __shfl_xor_sync(0xffffffffu, bv, o);
            int   oi = __shfl_xor_sync(0xffffffffu, bi, o);
            if (ov > bv || (ov == bv && oi < bi)) { bv = ov; bi = oi; }
        }
        topv[k] = bv; topi[k] = bi;
        if      (bi == lane)      v0 = -INFINITY;
        else if (bi == lane + 32) v1 = -INFINITY;
    }

    float ssum = 0.0f, ev[TOPK];
#pragma unroll
    for (int k = 0; k < TOPK; k++) { ev[k] = __expf(topv[k] - topv[0]); ssum += ev[k]; }
    float invt = __frcp_rn(ssum);

#pragma unroll
    for (int k = 0; k < TOPK; k++) {
        if (lane == k) {
            out_rtr[(size_t)b * TOPK + k] = ev[k] * invt;
            out_idx[(size_t)b * TOPK + k] = (float)topi[k];
        }
    }
}

// ---------------------------------------------------------------------------
extern "C" void kernel_launch(void* const* d_in, const int* in_sizes, int n_in,
                              void* d_out, int out_size) {
    const float* mh      = (const float*)d_in[0];
    const float* noise   = (const float*)d_in[1];
    const float* W_route = (const float*)d_in[2];
    const float* b_route = (const float*)d_in[3];
    const float* W_noise = (const float*)d_in[4];
    const float* b_noise = (const float*)d_in[5];
    float* out = (float*)d_out;

    pool_kernel<<<(NB * NC) / 8, 256>>>(mh);
    router_kernel<<<NB / ROWS, 256>>>(noise, W_route, b_route, W_noise, b_noise, out);
}